// round 1
// baseline (speedup 1.0000x reference)
#include <cuda_runtime.h>
#include <cstdint>

#define B_   24
#define NA_  50
#define T_   10
#define NV_  196
#define D_   512
#define M_   (B_*NA_)        // 1200 audio rows
#define N_   (B_*T_*NV_)     // 47040 visual rows (GEMM columns)
#define G_   (B_*T_)         // 240 (y,t) groups

#define BM 128
#define BN 128
#define BK 8
#define NTM 10               // ceil(1200/128)
#define NTN 368              // ceil(47040/128)
#define NKC (D_/BK)          // 64 k-chunks

// ---------------- device scratch (static, no allocations) ----------------
__device__ float        g_Anorm[M_ * D_];          // 2.4 MB
__device__ float        g_Vnorm[(size_t)N_ * D_];  // 96 MB
__device__ unsigned int g_maxvis[M_ * G_];         // 288000 encoded-float maxes
__device__ float        g_sumsq[NTM * NTN];        // per-CTA partial sum of min(s,0)^2
__device__ float        g_clip[B_ * B_];           // clip_sims
__device__ float        g_selsum[B_];              // diagonal tanh sums
__device__ int          g_fraccnt;                 // count raw_diff > 0

// monotone float<->uint encoding for atomicMax over signed floats
__device__ __forceinline__ unsigned int encf(float f) {
    unsigned int u = __float_as_uint(f);
    return (u & 0x80000000u) ? ~u : (u | 0x80000000u);
}
__device__ __forceinline__ float decf(unsigned int e) {
    unsigned int u = (e & 0x80000000u) ? (e & 0x7fffffffu) : ~e;
    return __uint_as_float(u);
}

// packed f32x2 helpers (Blackwell FFMA2 path — PTX only)
__device__ __forceinline__ unsigned long long pack2dup(float x) {
    unsigned long long r;
    asm("mov.b64 %0, {%1, %2};" : "=l"(r) : "f"(x), "f"(x));
    return r;
}
__device__ __forceinline__ void fma2(unsigned long long& d,
                                     unsigned long long a,
                                     unsigned long long b) {
    asm("fma.rn.f32x2 %0, %1, %2, %0;" : "+l"(d) : "l"(a), "l"(b));
}
__device__ __forceinline__ float2 unpack2(unsigned long long v) {
    float x, y;
    asm("mov.b64 {%0, %1}, %2;" : "=f"(x), "=f"(y) : "l"(v));
    return make_float2(x, y);
}

// ---------------- kernel 0: init (maxvis sentinel + counters) ----------------
__global__ void init_kernel() {
    int i = blockIdx.x * blockDim.x + threadIdx.x;
    if (i < M_ * G_) g_maxvis[i] = 0u;   // encodes "less than any real float"
    if (i == 0) g_fraccnt = 0;
}

// ---------------- kernel 1: row L2-normalize (128 thr/row, 1 row/block) ------
__global__ void norm_rows(const float* __restrict__ in, int which) {
    float* out = which ? g_Vnorm : g_Anorm;
    size_t row = blockIdx.x;
    const float4* ip = reinterpret_cast<const float4*>(in + row * D_);
    float4 v = ip[threadIdx.x];
    float s = v.x * v.x + v.y * v.y + v.z * v.z + v.w * v.w;
#pragma unroll
    for (int o = 16; o; o >>= 1) s += __shfl_xor_sync(0xffffffffu, s, o);
    __shared__ float ws[4];
    __shared__ float sinv;
    if ((threadIdx.x & 31) == 0) ws[threadIdx.x >> 5] = s;
    __syncthreads();
    if (threadIdx.x == 0) {
        float t = ws[0] + ws[1] + ws[2] + ws[3];
        sinv = 1.0f / fmaxf(sqrtf(t), 1e-12f);
    }
    __syncthreads();
    float iv = sinv;
    float4 o4 = make_float4(v.x * iv, v.y * iv, v.z * iv, v.w * iv);
    reinterpret_cast<float4*>(out + row * D_)[threadIdx.x] = o4;
}

// ---------------- kernel 2: GEMM + fused segmented-max / sumsq epilogue ------
__global__ __launch_bounds__(256)
void gemm_fused(const float* __restrict__ tempP) {
    __shared__ __align__(16) float As[2][BK][BM];
    __shared__ __align__(16) float Bs[2][BK][BN];

    const int tid = threadIdx.x;
    const int tx = tid & 15;        // column group of microtile
    const int ty = tid >> 4;        // row group of microtile
    const int rm0 = blockIdx.x * BM;
    const int cn0 = blockIdx.y * BN;

    // loader mapping: each thread loads one float4 of A and one of B per chunk
    const int lrow = tid >> 1;            // 0..127 (tile row / tile col)
    const int lf4  = (tid & 1) * 4;       // 0 or 4 within BK=8
    const bool aval = (rm0 + lrow) < M_;
    const bool bval = (cn0 + lrow) < N_;
    const float* Aptr = g_Anorm + (size_t)(rm0 + lrow) * D_ + lf4;
    const float* Bptr = g_Vnorm + (size_t)(cn0 + lrow) * D_ + lf4;

    unsigned long long acc[8][4];
#pragma unroll
    for (int i = 0; i < 8; i++)
#pragma unroll
        for (int j = 0; j < 4; j++) acc[i][j] = 0ull;

    // prologue: chunk 0 -> buffer 0
    {
        float4 av = aval ? *reinterpret_cast<const float4*>(Aptr) : make_float4(0, 0, 0, 0);
        float4 bv = bval ? *reinterpret_cast<const float4*>(Bptr) : make_float4(0, 0, 0, 0);
        As[0][lf4 + 0][lrow] = av.x; As[0][lf4 + 1][lrow] = av.y;
        As[0][lf4 + 2][lrow] = av.z; As[0][lf4 + 3][lrow] = av.w;
        Bs[0][lf4 + 0][lrow] = bv.x; Bs[0][lf4 + 1][lrow] = bv.y;
        Bs[0][lf4 + 2][lrow] = bv.z; Bs[0][lf4 + 3][lrow] = bv.w;
    }
    __syncthreads();

#pragma unroll 2
    for (int kc = 0; kc < NKC; ++kc) {
        const int cur = kc & 1;
        float4 na = make_float4(0, 0, 0, 0), nb = make_float4(0, 0, 0, 0);
        if (kc + 1 < NKC) {
            if (aval) na = *reinterpret_cast<const float4*>(Aptr + (kc + 1) * BK);
            if (bval) nb = *reinterpret_cast<const float4*>(Bptr + (kc + 1) * BK);
        }
#pragma unroll
        for (int kk = 0; kk < BK; ++kk) {
            float4 a0 = *reinterpret_cast<const float4*>(&As[cur][kk][ty * 8]);
            float4 a1 = *reinterpret_cast<const float4*>(&As[cur][kk][ty * 8 + 4]);
            ulonglong2 b0 = *reinterpret_cast<const ulonglong2*>(&Bs[cur][kk][tx * 8]);
            ulonglong2 b1 = *reinterpret_cast<const ulonglong2*>(&Bs[cur][kk][tx * 8 + 4]);
            unsigned long long bb[4] = {b0.x, b0.y, b1.x, b1.y};
            float a[8] = {a0.x, a0.y, a0.z, a0.w, a1.x, a1.y, a1.z, a1.w};
#pragma unroll
            for (int i = 0; i < 8; i++) {
                unsigned long long ai = pack2dup(a[i]);
#pragma unroll
                for (int j = 0; j < 4; j++) fma2(acc[i][j], ai, bb[j]);
            }
        }
        if (kc + 1 < NKC) {
            const int nxt = cur ^ 1;
            As[nxt][lf4 + 0][lrow] = na.x; As[nxt][lf4 + 1][lrow] = na.y;
            As[nxt][lf4 + 2][lrow] = na.z; As[nxt][lf4 + 3][lrow] = na.w;
            Bs[nxt][lf4 + 0][lrow] = nb.x; Bs[nxt][lf4 + 1][lrow] = nb.y;
            Bs[nxt][lf4 + 2][lrow] = nb.z; Bs[nxt][lf4 + 3][lrow] = nb.w;
        }
        __syncthreads();
    }

    // ---- fused epilogue ----
    const float invT = 1.0f / __ldg(tempP);
    const int gBase = cn0 / NV_;
    const int bnd   = (gBase + 1) * NV_;   // column where group gBase+1 starts
    float ssq = 0.f;

#pragma unroll
    for (int i = 0; i < 8; i++) {
        const int row = rm0 + ty * 8 + i;
        float mx0 = -3.0e38f, mx1 = -3.0e38f;
#pragma unroll
        for (int j = 0; j < 4; j++) {
            float2 p = unpack2(acc[i][j]);
            int c0 = cn0 + tx * 8 + 2 * j;
            if (row < M_ && c0 < N_) {
                float s = p.x * invT;
                float nn = fmaxf(fminf(s, 0.f), -20.f);
                ssq += nn * nn;
                if (c0 < bnd) mx0 = fmaxf(mx0, s); else mx1 = fmaxf(mx1, s);
            }
            int c1 = c0 + 1;
            if (row < M_ && c1 < N_) {
                float s = p.y * invT;
                float nn = fmaxf(fminf(s, 0.f), -20.f);
                ssq += nn * nn;
                if (c1 < bnd) mx0 = fmaxf(mx0, s); else mx1 = fmaxf(mx1, s);
            }
        }
        // reduce across the 16 tx-lanes (lane bits 0..3 of the half-warp)
#pragma unroll
        for (int o = 8; o; o >>= 1) {
            mx0 = fmaxf(mx0, __shfl_xor_sync(0xffffffffu, mx0, o));
            mx1 = fmaxf(mx1, __shfl_xor_sync(0xffffffffu, mx1, o));
        }
        if (tx == 0 && row < M_) {
            if (mx0 > -1.0e38f) atomicMax(&g_maxvis[row * G_ + gBase], encf(mx0));
            if (mx1 > -1.0e38f) atomicMax(&g_maxvis[row * G_ + gBase + 1], encf(mx1));
        }
    }

    // block-reduce ssq (fixed order -> deterministic), one partial per CTA
#pragma unroll
    for (int o = 16; o; o >>= 1) ssq += __shfl_xor_sync(0xffffffffu, ssq, o);
    __shared__ float sred[8];
    if ((tid & 31) == 0) sred[tid >> 5] = ssq;
    __syncthreads();
    if (tid == 0) {
        float t = 0.f;
#pragma unroll
        for (int i = 0; i < 8; i++) t += sred[i];
        g_sumsq[blockIdx.y * NTM + blockIdx.x] = t;
    }
}

// ---------------- kernel 3: temporal aggregation per (x,y) pair --------------
__global__ void stage2(const float* __restrict__ sfP, const float* __restrict__ thP) {
    const int p = blockIdx.x;
    const int x = p / B_;
    const int y = p % B_;
    const int a = threadIdx.x;   // 64 threads, a<50 active

    const float th = 1.0f / (1.0f + expf(-__ldg(thP)));
    const float sf = __ldg(sfP);

    float token = 0.f, sr = 0.f;
    int cnt = 0;
    if (a < NA_) {
        float wsum = 0.f, ws = 0.f;
        const int base = (x * NA_ + a) * G_ + y * T_;
#pragma unroll
        for (int t = 0; t < T_; t++) {
            float m = decf(g_maxvis[base + t]);
            float raw = m - th;
            float sel = fmaxf(raw, 0.f) * sf;
            ws += m * sel;
            wsum += sel;
            cnt += (raw > 0.f) ? 1 : 0;
            if (x == y) sr += 0.5f * (tanhf(20.f * raw) + 1.f);
        }
        token = ws / fmaxf(wsum, 1e-6f);
    }
    __shared__ float st[64], ss[64];
    __shared__ int sc[64];
    st[threadIdx.x] = token; ss[threadIdx.x] = sr; sc[threadIdx.x] = cnt;
    __syncthreads();
    if (threadIdx.x == 0) {
        float ts = 0.f, srs = 0.f; int c = 0;
        for (int i = 0; i < 64; i++) { ts += st[i]; srs += ss[i]; c += sc[i]; }
        g_clip[x * B_ + y] = ts / (float)NA_;
        atomicAdd(&g_fraccnt, c);          // integer atomic: deterministic
        if (x == y) g_selsum[x] = srs;
    }
}

// ---------------- kernel 4: finalize 5 scalars --------------------------------
__global__ void stage3(float* __restrict__ out,
                       const float* __restrict__ tempP,
                       const float* __restrict__ sfP,
                       const float* __restrict__ thP) {
    const int t = threadIdx.x;   // 32 threads
    __shared__ float la[B_], lv[B_];
    __shared__ float sp[32];

    if (t < B_) {
        // row t of clip_sims (a2v)
        float m = -3.0e38f;
        for (int j = 0; j < B_; j++) m = fmaxf(m, g_clip[t * B_ + j]);
        float s = 0.f;
        for (int j = 0; j < B_; j++) s += expf(g_clip[t * B_ + j] - m);
        la[t] = -(g_clip[t * B_ + t] - (logf(s) + m));
        // column t of clip_sims (v2a)
        float m2 = -3.0e38f;
        for (int j = 0; j < B_; j++) m2 = fmaxf(m2, g_clip[j * B_ + t]);
        float s2 = 0.f;
        for (int j = 0; j < B_; j++) s2 += expf(g_clip[j * B_ + t] - m2);
        lv[t] = -(g_clip[t * B_ + t] - (logf(s2) + m2));
    }
    float acc = 0.f;
    for (int i = t; i < NTM * NTN; i += 32) acc += g_sumsq[i];
    sp[t] = acc;
    __syncthreads();

    if (t == 0) {
        float sumsq = 0.f;
        for (int i = 0; i < 32; i++) sumsq += sp[i];

        float contr = 0.f;
        for (int i = 0; i < B_; i++) contr += la[i] + lv[i];
        contr = contr / (float)B_ * 0.5f;

        float temp = *tempP, sf = *sfP;
        float th = 1.0f / (1.0f + expf(-(*thP)));

        float l_nonneg = sumsq / 56448000.0f;   // B*B*NA*T*NV
        float lt = logf(temp);
        float tlow = fmaxf(-lt, 0.f);  tlow *= tlow;
        float thigh = fmaxf(lt - logf(4.0f), 0.f); thigh *= thigh;
        float l_cal = tlow + thigh;
        float a1 = fmaxf(th - 0.9f, 0.f), a2 = fmaxf(0.1f - th, 0.f);
        float l_th = a1 * a1 + a2 * a2;
        float b1 = fmaxf(sf - 20.f, 0.f), b2 = fmaxf(1.f - sf, 0.f);
        float l_sc = b1 * b1 + b2 * b2;
        float reg = 0.15f * l_nonneg + 2.0f * l_cal + 0.1f * l_th + 0.1f * l_sc;

        float frac = (float)g_fraccnt / 288000.0f;   // B*B*NA*T

        float selmean = 0.f;
        for (int i = 0; i < B_; i++) selmean += g_selsum[i];
        selmean /= 12000.0f;                          // B*NA*T
        float selrew = -0.1f * log1pf(selmean);

        float total = selrew + contr + reg;
        out[0] = total;
        out[1] = contr;
        out[2] = reg;
        out[3] = frac;
        out[4] = selrew;
    }
}

// ---------------- launch ------------------------------------------------------
extern "C" void kernel_launch(void* const* d_in, const int* in_sizes, int n_in,
                              void* d_out, int out_size) {
    const float* audio  = (const float*)d_in[0];
    const float* visual = (const float*)d_in[1];
    const float* tempP  = (const float*)d_in[2];
    const float* sfP    = (const float*)d_in[3];
    const float* thP    = (const float*)d_in[4];
    float* out = (float*)d_out;

    init_kernel<<<(M_ * G_ + 255) / 256, 256>>>();
    norm_rows<<<M_, 128>>>(audio, 0);
    norm_rows<<<N_, 128>>>(visual, 1);

    dim3 grid(NTM, NTN);   // x = row tiles (fast) -> 10 consecutive CTAs share a V tile in L2
    gemm_fused<<<grid, 256>>>(tempP);

    stage2<<<B_ * B_, 64>>>(sfP, thP);
    stage3<<<1, 32>>>(out, tempP, sfP, thP);
}

// round 2
// speedup vs baseline: 1.0003x; 1.0003x over previous
#include <cuda_runtime.h>
#include <cstdint>

#define B_   24
#define NA_  50
#define T_   10
#define NV_  196
#define D_   512
#define M_   (B_*NA_)        // 1200 audio rows
#define N_   (B_*T_*NV_)     // 47040 visual rows (GEMM columns)
#define G_   (B_*T_)         // 240 (y,t) groups

#define BM 128
#define BN 128
#define BK 8
#define NTM 10               // ceil(1200/128)
#define NTN 368              // ceil(47040/128)
#define NKC (D_/BK)          // 64 k-chunks

// ---------------- device scratch (static, no allocations) ----------------
__device__ float        g_Anorm[M_ * D_];          // 2.4 MB
__device__ float        g_Vnorm[(size_t)N_ * D_];  // 96 MB
__device__ unsigned int g_maxvis[M_ * G_];         // 288000 encoded-float maxes
__device__ float        g_sumsq[NTM * NTN];        // per-CTA partial sum of min(s,0)^2
__device__ float        g_clip[B_ * B_];           // clip_sims
__device__ float        g_selsum[B_];              // diagonal tanh sums
__device__ int          g_fraccnt;                 // count raw_diff > 0

// monotone float<->uint encoding for atomicMax over signed floats
__device__ __forceinline__ unsigned int encf(float f) {
    unsigned int u = __float_as_uint(f);
    return (u & 0x80000000u) ? ~u : (u | 0x80000000u);
}
__device__ __forceinline__ float decf(unsigned int e) {
    unsigned int u = (e & 0x80000000u) ? (e & 0x7fffffffu) : ~e;
    return __uint_as_float(u);
}

// packed f32x2 helpers (Blackwell FFMA2 path — PTX only)
__device__ __forceinline__ unsigned long long pack2dup(float x) {
    unsigned long long r;
    asm("mov.b64 %0, {%1, %2};" : "=l"(r) : "f"(x), "f"(x));
    return r;
}
__device__ __forceinline__ void fma2(unsigned long long& d,
                                     unsigned long long a,
                                     unsigned long long b) {
    asm("fma.rn.f32x2 %0, %1, %2, %0;" : "+l"(d) : "l"(a), "l"(b));
}
__device__ __forceinline__ float2 unpack2(unsigned long long v) {
    float x, y;
    asm("mov.b64 {%0, %1}, %2;" : "=f"(x), "=f"(y) : "l"(v));
    return make_float2(x, y);
}

// ---------------- kernel 0: init (maxvis sentinel + counters) ----------------
__global__ void init_kernel() {
    int i = blockIdx.x * blockDim.x + threadIdx.x;
    if (i < M_ * G_) g_maxvis[i] = 0u;   // encodes "less than any real float"
    if (i == 0) g_fraccnt = 0;
}

// ---------------- kernel 1: row L2-normalize (128 thr/row, 1 row/block) ------
__global__ void norm_rows(const float* __restrict__ in, int which) {
    float* out = which ? g_Vnorm : g_Anorm;
    size_t row = blockIdx.x;
    const float4* ip = reinterpret_cast<const float4*>(in + row * D_);
    float4 v = ip[threadIdx.x];
    float s = v.x * v.x + v.y * v.y + v.z * v.z + v.w * v.w;
#pragma unroll
    for (int o = 16; o; o >>= 1) s += __shfl_xor_sync(0xffffffffu, s, o);
    __shared__ float ws[4];
    __shared__ float sinv;
    if ((threadIdx.x & 31) == 0) ws[threadIdx.x >> 5] = s;
    __syncthreads();
    if (threadIdx.x == 0) {
        float t = ws[0] + ws[1] + ws[2] + ws[3];
        sinv = 1.0f / fmaxf(sqrtf(t), 1e-12f);
    }
    __syncthreads();
    float iv = sinv;
    float4 o4 = make_float4(v.x * iv, v.y * iv, v.z * iv, v.w * iv);
    reinterpret_cast<float4*>(out + row * D_)[threadIdx.x] = o4;
}

// ---------------- kernel 2: GEMM + fused segmented-max / sumsq epilogue ------
__global__ __launch_bounds__(256)
void gemm_fused(const float* __restrict__ tempP) {
    __shared__ __align__(16) float As[2][BK][BM];
    __shared__ __align__(16) float Bs[2][BK][BN];

    const int tid = threadIdx.x;
    const int tx = tid & 15;        // column group of microtile
    const int ty = tid >> 4;        // row group of microtile
    const int rm0 = blockIdx.x * BM;
    const int cn0 = blockIdx.y * BN;

    // loader mapping: each thread loads one float4 of A and one of B per chunk
    const int lrow = tid >> 1;            // 0..127 (tile row / tile col)
    const int lf4  = (tid & 1) * 4;       // 0 or 4 within BK=8
    const bool aval = (rm0 + lrow) < M_;
    const bool bval = (cn0 + lrow) < N_;
    const float* Aptr = g_Anorm + (size_t)(rm0 + lrow) * D_ + lf4;
    const float* Bptr = g_Vnorm + (size_t)(cn0 + lrow) * D_ + lf4;

    unsigned long long acc[8][4];
#pragma unroll
    for (int i = 0; i < 8; i++)
#pragma unroll
        for (int j = 0; j < 4; j++) acc[i][j] = 0ull;

    // prologue: chunk 0 -> buffer 0
    {
        float4 av = aval ? *reinterpret_cast<const float4*>(Aptr) : make_float4(0, 0, 0, 0);
        float4 bv = bval ? *reinterpret_cast<const float4*>(Bptr) : make_float4(0, 0, 0, 0);
        As[0][lf4 + 0][lrow] = av.x; As[0][lf4 + 1][lrow] = av.y;
        As[0][lf4 + 2][lrow] = av.z; As[0][lf4 + 3][lrow] = av.w;
        Bs[0][lf4 + 0][lrow] = bv.x; Bs[0][lf4 + 1][lrow] = bv.y;
        Bs[0][lf4 + 2][lrow] = bv.z; Bs[0][lf4 + 3][lrow] = bv.w;
    }
    __syncthreads();

#pragma unroll 2
    for (int kc = 0; kc < NKC; ++kc) {
        const int cur = kc & 1;
        float4 na = make_float4(0, 0, 0, 0), nb = make_float4(0, 0, 0, 0);
        if (kc + 1 < NKC) {
            if (aval) na = *reinterpret_cast<const float4*>(Aptr + (kc + 1) * BK);
            if (bval) nb = *reinterpret_cast<const float4*>(Bptr + (kc + 1) * BK);
        }
#pragma unroll
        for (int kk = 0; kk < BK; ++kk) {
            float4 a0 = *reinterpret_cast<const float4*>(&As[cur][kk][ty * 8]);
            float4 a1 = *reinterpret_cast<const float4*>(&As[cur][kk][ty * 8 + 4]);
            ulonglong2 b0 = *reinterpret_cast<const ulonglong2*>(&Bs[cur][kk][tx * 8]);
            ulonglong2 b1 = *reinterpret_cast<const ulonglong2*>(&Bs[cur][kk][tx * 8 + 4]);
            unsigned long long bb[4] = {b0.x, b0.y, b1.x, b1.y};
            float a[8] = {a0.x, a0.y, a0.z, a0.w, a1.x, a1.y, a1.z, a1.w};
#pragma unroll
            for (int i = 0; i < 8; i++) {
                unsigned long long ai = pack2dup(a[i]);
#pragma unroll
                for (int j = 0; j < 4; j++) fma2(acc[i][j], ai, bb[j]);
            }
        }
        if (kc + 1 < NKC) {
            const int nxt = cur ^ 1;
            As[nxt][lf4 + 0][lrow] = na.x; As[nxt][lf4 + 1][lrow] = na.y;
            As[nxt][lf4 + 2][lrow] = na.z; As[nxt][lf4 + 3][lrow] = na.w;
            Bs[nxt][lf4 + 0][lrow] = nb.x; Bs[nxt][lf4 + 1][lrow] = nb.y;
            Bs[nxt][lf4 + 2][lrow] = nb.z; Bs[nxt][lf4 + 3][lrow] = nb.w;
        }
        __syncthreads();
    }

    // ---- fused epilogue ----
    const float invT = 1.0f / __ldg(tempP);
    const int gBase = cn0 / NV_;
    const int bnd   = (gBase + 1) * NV_;   // column where group gBase+1 starts
    float ssq = 0.f;

#pragma unroll
    for (int i = 0; i < 8; i++) {
        const int row = rm0 + ty * 8 + i;
        float mx0 = -3.0e38f, mx1 = -3.0e38f;
#pragma unroll
        for (int j = 0; j < 4; j++) {
            float2 p = unpack2(acc[i][j]);
            int c0 = cn0 + tx * 8 + 2 * j;
            if (row < M_ && c0 < N_) {
                float s = p.x * invT;
                float nn = fmaxf(fminf(s, 0.f), -20.f);
                ssq += nn * nn;
                if (c0 < bnd) mx0 = fmaxf(mx0, s); else mx1 = fmaxf(mx1, s);
            }
            int c1 = c0 + 1;
            if (row < M_ && c1 < N_) {
                float s = p.y * invT;
                float nn = fmaxf(fminf(s, 0.f), -20.f);
                ssq += nn * nn;
                if (c1 < bnd) mx0 = fmaxf(mx0, s); else mx1 = fmaxf(mx1, s);
            }
        }
        // reduce across the 16 tx-lanes (lane bits 0..3 of the half-warp)
#pragma unroll
        for (int o = 8; o; o >>= 1) {
            mx0 = fmaxf(mx0, __shfl_xor_sync(0xffffffffu, mx0, o));
            mx1 = fmaxf(mx1, __shfl_xor_sync(0xffffffffu, mx1, o));
        }
        if (tx == 0 && row < M_) {
            if (mx0 > -1.0e38f) atomicMax(&g_maxvis[row * G_ + gBase], encf(mx0));
            if (mx1 > -1.0e38f) atomicMax(&g_maxvis[row * G_ + gBase + 1], encf(mx1));
        }
    }

    // block-reduce ssq (fixed order -> deterministic), one partial per CTA
#pragma unroll
    for (int o = 16; o; o >>= 1) ssq += __shfl_xor_sync(0xffffffffu, ssq, o);
    __shared__ float sred[8];
    if ((tid & 31) == 0) sred[tid >> 5] = ssq;
    __syncthreads();
    if (tid == 0) {
        float t = 0.f;
#pragma unroll
        for (int i = 0; i < 8; i++) t += sred[i];
        g_sumsq[blockIdx.y * NTM + blockIdx.x] = t;
    }
}

// ---------------- kernel 3: temporal aggregation per (x,y) pair --------------
__global__ void stage2(const float* __restrict__ sfP, const float* __restrict__ thP) {
    const int p = blockIdx.x;
    const int x = p / B_;
    const int y = p % B_;
    const int a = threadIdx.x;   // 64 threads, a<50 active

    const float th = 1.0f / (1.0f + expf(-__ldg(thP)));
    const float sf = __ldg(sfP);

    float token = 0.f, sr = 0.f;
    int cnt = 0;
    if (a < NA_) {
        float wsum = 0.f, ws = 0.f;
        const int base = (x * NA_ + a) * G_ + y * T_;
#pragma unroll
        for (int t = 0; t < T_; t++) {
            float m = decf(g_maxvis[base + t]);
            float raw = m - th;
            float sel = fmaxf(raw, 0.f) * sf;
            ws += m * sel;
            wsum += sel;
            cnt += (raw > 0.f) ? 1 : 0;
            if (x == y) sr += 0.5f * (tanhf(20.f * raw) + 1.f);
        }
        token = ws / fmaxf(wsum, 1e-6f);
    }
    __shared__ float st[64], ss[64];
    __shared__ int sc[64];
    st[threadIdx.x] = token; ss[threadIdx.x] = sr; sc[threadIdx.x] = cnt;
    __syncthreads();
    if (threadIdx.x == 0) {
        float ts = 0.f, srs = 0.f; int c = 0;
        for (int i = 0; i < 64; i++) { ts += st[i]; srs += ss[i]; c += sc[i]; }
        g_clip[x * B_ + y] = ts / (float)NA_;
        atomicAdd(&g_fraccnt, c);          // integer atomic: deterministic
        if (x == y) g_selsum[x] = srs;
    }
}

// ---------------- kernel 4: finalize 5 scalars --------------------------------
__global__ void stage3(float* __restrict__ out,
                       const float* __restrict__ tempP,
                       const float* __restrict__ sfP,
                       const float* __restrict__ thP) {
    const int t = threadIdx.x;   // 32 threads
    __shared__ float la[B_], lv[B_];
    __shared__ float sp[32];

    if (t < B_) {
        // row t of clip_sims (a2v)
        float m = -3.0e38f;
        for (int j = 0; j < B_; j++) m = fmaxf(m, g_clip[t * B_ + j]);
        float s = 0.f;
        for (int j = 0; j < B_; j++) s += expf(g_clip[t * B_ + j] - m);
        la[t] = -(g_clip[t * B_ + t] - (logf(s) + m));
        // column t of clip_sims (v2a)
        float m2 = -3.0e38f;
        for (int j = 0; j < B_; j++) m2 = fmaxf(m2, g_clip[j * B_ + t]);
        float s2 = 0.f;
        for (int j = 0; j < B_; j++) s2 += expf(g_clip[j * B_ + t] - m2);
        lv[t] = -(g_clip[t * B_ + t] - (logf(s2) + m2));
    }
    float acc = 0.f;
    for (int i = t; i < NTM * NTN; i += 32) acc += g_sumsq[i];
    sp[t] = acc;
    __syncthreads();

    if (t == 0) {
        float sumsq = 0.f;
        for (int i = 0; i < 32; i++) sumsq += sp[i];

        float contr = 0.f;
        for (int i = 0; i < B_; i++) contr += la[i] + lv[i];
        contr = contr / (float)B_ * 0.5f;

        float temp = *tempP, sf = *sfP;
        float th = 1.0f / (1.0f + expf(-(*thP)));

        float l_nonneg = sumsq / 56448000.0f;   // B*B*NA*T*NV
        float lt = logf(temp);
        float tlow = fmaxf(-lt, 0.f);  tlow *= tlow;
        float thigh = fmaxf(lt - logf(4.0f), 0.f); thigh *= thigh;
        float l_cal = tlow + thigh;
        float a1 = fmaxf(th - 0.9f, 0.f), a2 = fmaxf(0.1f - th, 0.f);
        float l_th = a1 * a1 + a2 * a2;
        float b1 = fmaxf(sf - 20.f, 0.f), b2 = fmaxf(1.f - sf, 0.f);
        float l_sc = b1 * b1 + b2 * b2;
        float reg = 0.15f * l_nonneg + 2.0f * l_cal + 0.1f * l_th + 0.1f * l_sc;

        float frac = (float)g_fraccnt / 288000.0f;   // B*B*NA*T

        float selmean = 0.f;
        for (int i = 0; i < B_; i++) selmean += g_selsum[i];
        selmean /= 12000.0f;                          // B*NA*T
        float selrew = -0.1f * log1pf(selmean);

        float total = selrew + contr + reg;
        out[0] = total;
        out[1] = contr;
        out[2] = reg;
        out[3] = frac;
        out[4] = selrew;
    }
}

// ---------------- launch ------------------------------------------------------
extern "C" void kernel_launch(void* const* d_in, const int* in_sizes, int n_in,
                              void* d_out, int out_size) {
    const float* audio  = (const float*)d_in[0];
    const float* visual = (const float*)d_in[1];
    const float* tempP  = (const float*)d_in[2];
    const float* sfP    = (const float*)d_in[3];
    const float* thP    = (const float*)d_in[4];
    float* out = (float*)d_out;

    init_kernel<<<(M_ * G_ + 255) / 256, 256>>>();
    norm_rows<<<M_, 128>>>(audio, 0);
    norm_rows<<<N_, 128>>>(visual, 1);

    dim3 grid(NTM, NTN);   // x = row tiles (fast) -> 10 consecutive CTAs share a V tile in L2
    gemm_fused<<<grid, 256>>>(tempP);

    stage2<<<B_ * B_, 64>>>(sfP, thP);
    stage3<<<1, 32>>>(out, tempP, sfP, thP);
}

// round 4
// speedup vs baseline: 2.6650x; 2.6642x over previous
#include <cuda_runtime.h>
#include <cuda.h>
#include <cuda_bf16.h>
#include <cstdint>

#define B_   24
#define NA_  50
#define T_   10
#define NV_  196
#define D_   512
#define M_   (B_*NA_)        // 1200
#define N_   (B_*T_*NV_)     // 47040
#define G_   (B_*T_)         // 240

#define NTM    10            // ceil(1200/128)
#define NTN    368           // ceil(47040/128)
#define NTILES (NTM*NTN)     // 3680
#define NSUMSQ NTILES
#define KCH    8             // 512/64 k-chunks per tile
#define GRID_  148
#define NSTAGE 3

#define TILE_BYTES_  16384   // 128 rows x 64 bf16 x 2B
#define STAGE_BYTES  (4*TILE_BYTES_)          // Ahi, Alo, Vhi, Vlo
#define SMEM_TOTAL   (NSTAGE*STAGE_BYTES)     // 196608

// ---------------- device scratch ----------------
__device__ __align__(128) __nv_bfloat16 g_Ahi[M_*D_];
__device__ __align__(128) __nv_bfloat16 g_Alo[M_*D_];
__device__ __align__(128) __nv_bfloat16 g_Vhi[(size_t)N_*D_];
__device__ __align__(128) __nv_bfloat16 g_Vlo[(size_t)N_*D_];
__device__ unsigned int  g_maxvis[M_*G_];
__device__ float         g_sumsq[NSUMSQ];
__device__ float         g_clip[B_*B_];
__device__ float         g_selsum[B_];
__device__ int           g_fraccnt;

// ---------------- PTX helpers (all non-'a' features) ----------------
__device__ __forceinline__ uint32_t smem_u32(const void* p) {
    uint32_t a;
    asm("{ .reg .u64 t; cvta.to.shared.u64 t, %1; cvt.u32.u64 %0, t; }" : "=r"(a) : "l"(p));
    return a;
}
#define MBARRIER_INIT(a, c) \
    asm volatile("mbarrier.init.shared.b64 [%0], %1;" :: "r"((uint32_t)(a)), "r"((uint32_t)(c)) : "memory")
#define MBARRIER_EXPECT_TX(a, b) \
    asm volatile("mbarrier.arrive.expect_tx.shared.b64 _, [%0], %1;" :: "r"((uint32_t)(a)), "r"((uint32_t)(b)) : "memory")
#define MBARRIER_WAIT_PARITY(a, ph) do { \
    uint32_t _m = (uint32_t)(a); uint32_t _p = (uint32_t)(ph); uint32_t _d; \
    asm volatile("{\n\t.reg .pred p;\n\t" \
        "mbarrier.try_wait.parity.acquire.cta.shared::cta.b64 p, [%1], %2;\n\t" \
        "selp.b32 %0, 1, 0, p;\n\t}" : "=r"(_d) : "r"(_m), "r"(_p) : "memory"); \
    if (!_d) { \
        asm volatile("{\n\t.reg .pred P1;\n\tWL_%=:\n\t" \
            "mbarrier.try_wait.parity.acquire.cta.shared::cta.b64 P1, [%0], %1, 0x989680;\n\t" \
            "@P1 bra.uni WD_%=;\n\tbra.uni WL_%=;\n\tWD_%=:\n\t}" \
            :: "r"(_m), "r"(_p) : "memory"); \
    } } while (0)
#define FENCE_PROXY_ASYNC() asm volatile("fence.proxy.async.shared::cta;" ::: "memory")

__device__ __forceinline__ void tma_ld_2d(uint32_t dst, const CUtensorMap* map,
                                          int cx, int cy, uint32_t mbar) {
    asm volatile(
        "cp.async.bulk.tensor.2d.shared::cta.global.tile.mbarrier::complete_tx::bytes "
        "[%0], [%1, {%2, %3}], [%4];"
        :: "r"(dst), "l"(map), "r"(cx), "r"(cy), "r"(mbar) : "memory");
}
__device__ __forceinline__ void ldsm4(uint32_t r[4], uint32_t addr) {
    asm volatile("ldmatrix.sync.aligned.m8n8.x4.shared.b16 {%0,%1,%2,%3}, [%4];"
        : "=r"(r[0]), "=r"(r[1]), "=r"(r[2]), "=r"(r[3]) : "r"(addr));
}
__device__ __forceinline__ void mma_bf16(float d[4], const uint32_t a[4], const uint32_t b[2]) {
    asm volatile("mma.sync.aligned.m16n8k16.row.col.f32.bf16.bf16.f32 "
        "{%0,%1,%2,%3}, {%4,%5,%6,%7}, {%8,%9}, {%0,%1,%2,%3};"
        : "+f"(d[0]), "+f"(d[1]), "+f"(d[2]), "+f"(d[3])
        : "r"(a[0]), "r"(a[1]), "r"(a[2]), "r"(a[3]), "r"(b[0]), "r"(b[1]));
}

// monotone float<->uint encoding for atomicMax over signed floats
__device__ __forceinline__ unsigned int encf(float f) {
    unsigned int u = __float_as_uint(f);
    return (u & 0x80000000u) ? ~u : (u | 0x80000000u);
}
__device__ __forceinline__ float decf(unsigned int e) {
    unsigned int u = (e & 0x80000000u) ? (e & 0x7fffffffu) : ~e;
    return __uint_as_float(u);
}

// ---------------- kernel 0: init ----------------
__global__ void init_kernel() {
    int i = blockIdx.x * blockDim.x + threadIdx.x;
    if (i < M_ * G_) g_maxvis[i] = 0u;
    if (i == 0) g_fraccnt = 0;
}

// ---------------- kernel 1: L2-normalize + hi/lo bf16 split ----------------
__global__ void norm_split(const float* __restrict__ in, int which) {
    __nv_bfloat16* hi = which ? g_Vhi : g_Ahi;
    __nv_bfloat16* lo = which ? g_Vlo : g_Alo;
    size_t row = blockIdx.x;
    float4 v = reinterpret_cast<const float4*>(in + row * D_)[threadIdx.x];
    float s = v.x * v.x + v.y * v.y + v.z * v.z + v.w * v.w;
#pragma unroll
    for (int o = 16; o; o >>= 1) s += __shfl_xor_sync(0xffffffffu, s, o);
    __shared__ float ws[4];
    __shared__ float sinv;
    if ((threadIdx.x & 31) == 0) ws[threadIdx.x >> 5] = s;
    __syncthreads();
    if (threadIdx.x == 0) sinv = 1.0f / fmaxf(sqrtf(ws[0] + ws[1] + ws[2] + ws[3]), 1e-12f);
    __syncthreads();
    float iv = sinv;
    float x0 = v.x * iv, x1 = v.y * iv, x2 = v.z * iv, x3 = v.w * iv;
    __nv_bfloat16 h0 = __float2bfloat16(x0), h1 = __float2bfloat16(x1);
    __nv_bfloat16 h2 = __float2bfloat16(x2), h3 = __float2bfloat16(x3);
    __nv_bfloat16 l0 = __float2bfloat16(x0 - __bfloat162float(h0));
    __nv_bfloat16 l1 = __float2bfloat16(x1 - __bfloat162float(h1));
    __nv_bfloat16 l2 = __float2bfloat16(x2 - __bfloat162float(h2));
    __nv_bfloat16 l3 = __float2bfloat16(x3 - __bfloat162float(h3));
    __nv_bfloat162 hA; hA.x = h0; hA.y = h1;
    __nv_bfloat162 hB; hB.x = h2; hB.y = h3;
    __nv_bfloat162 lA; lA.x = l0; lA.y = l1;
    __nv_bfloat162 lB; lB.x = l2; lB.y = l3;
    uint2 hu, lu;
    hu.x = *reinterpret_cast<uint32_t*>(&hA); hu.y = *reinterpret_cast<uint32_t*>(&hB);
    lu.x = *reinterpret_cast<uint32_t*>(&lA); lu.y = *reinterpret_cast<uint32_t*>(&lB);
    *reinterpret_cast<uint2*>(hi + row * D_ + threadIdx.x * 4) = hu;
    *reinterpret_cast<uint2*>(lo + row * D_ + threadIdx.x * 4) = lu;
}

// ---------------- kernel 2: persistent HMMA GEMM + fused epilogue ------------
__global__ __launch_bounds__(256, 1)
void gemm_mma(const __grid_constant__ CUtensorMap tmAhi,
              const __grid_constant__ CUtensorMap tmAlo,
              const __grid_constant__ CUtensorMap tmVhi,
              const __grid_constant__ CUtensorMap tmVlo,
              const float* __restrict__ tempP) {
    extern __shared__ __align__(1024) char dsmem[];
    __shared__ uint64_t s_bar[NSTAGE];
    __shared__ float    sred[8];

    const int tid   = threadIdx.x;
    const int lane  = tid & 31;
    const int wid   = tid >> 5;
    const int warpM = wid & 3;        // 4 row groups of 32
    const int warpN = wid >> 2;       // 2 col groups of 64
    const uint32_t sbase = smem_u32(dsmem);
    uint32_t FULL[NSTAGE];
#pragma unroll
    for (int i = 0; i < NSTAGE; i++) FULL[i] = smem_u32(&s_bar[i]);

    if (tid == 0) {
#pragma unroll
        for (int i = 0; i < NSTAGE; i++) MBARRIER_INIT(FULL[i], 1);
        FENCE_PROXY_ASYNC();
    }
    __syncthreads();

    const float invT = 1.0f / __ldg(tempP);
    const int bx = blockIdx.x;
    const int ntiles = (NTILES - 1 - bx) / GRID_ + 1;
    const int totChunks = ntiles * KCH;

    // per-thread ldmatrix row addressing (within a 128x64 SW128 tile)
    // A: rows warpM*32 + mt*16 + (lane&15) ; B: rows warpN*64 + p*16 + (lane&15)
    int rA[2], rB[4];
    uint32_t swA[2], swB[4];
#pragma unroll
    for (int mt = 0; mt < 2; mt++) {
        int r = warpM * 32 + mt * 16 + (lane & 15);
        rA[mt] = r * 128; swA[mt] = (r & 7) << 4;
    }
#pragma unroll
    for (int p = 0; p < 4; p++) {
        int r = warpN * 64 + p * 16 + (lane & 15);
        rB[p] = r * 128; swB[p] = (r & 7) << 4;
    }
    const uint32_t laneHi = (lane & 16);   // 0 or 16 bytes (k8 half select)

    // producer helper state lives in registers of tid 0 only
    auto fill = [&](int nf) {
        const int s  = bx + (nf / KCH) * GRID_;
        const int c  = nf % KCH;
        const int st = nf % NSTAGE;
        const int rm0 = (s % NTM) * 128;
        const int cn0 = (s / NTM) * 128;
        const uint32_t stg = sbase + st * STAGE_BYTES;
        const int k0 = c * 64;
        MBARRIER_EXPECT_TX(FULL[st], STAGE_BYTES);
        tma_ld_2d(stg + 0 * TILE_BYTES_, &tmAhi, k0, rm0, FULL[st]);
        tma_ld_2d(stg + 1 * TILE_BYTES_, &tmAlo, k0, rm0, FULL[st]);
        tma_ld_2d(stg + 2 * TILE_BYTES_, &tmVhi, k0, cn0, FULL[st]);
        tma_ld_2d(stg + 3 * TILE_BYTES_, &tmVlo, k0, cn0, FULL[st]);
    };

    if (tid == 0) {
        const int pre = totChunks < NSTAGE ? totChunks : NSTAGE;
        for (int i = 0; i < pre; i++) fill(i);
    }

    int gc = 0;
    for (int s = bx; s < NTILES; s += GRID_) {
        const int rm0 = (s % NTM) * 128;
        const int cn0 = (s / NTM) * 128;

        float acc[2][8][4];
#pragma unroll
        for (int mt = 0; mt < 2; mt++)
#pragma unroll
            for (int nt = 0; nt < 8; nt++)
#pragma unroll
                for (int e = 0; e < 4; e++) acc[mt][nt][e] = 0.f;

        for (int c = 0; c < KCH; c++, gc++) {
            const int st = gc % NSTAGE;
            MBARRIER_WAIT_PARITY(FULL[st], (gc / NSTAGE) & 1);
            const uint32_t stg  = sbase + st * STAGE_BYTES;
            const uint32_t pAhi = stg;
            const uint32_t pAlo = stg + 1 * TILE_BYTES_;
            const uint32_t pVhi = stg + 2 * TILE_BYTES_;
            const uint32_t pVlo = stg + 3 * TILE_BYTES_;

#pragma unroll
            for (int ks = 0; ks < 4; ks++) {
                const uint32_t kbb = ks * 32 + laneHi;
                uint32_t ahi[2][4], alo[2][4];
#pragma unroll
                for (int mt = 0; mt < 2; mt++) {
                    ldsm4(ahi[mt], pAhi + rA[mt] + (kbb ^ swA[mt]));
                    ldsm4(alo[mt], pAlo + rA[mt] + (kbb ^ swA[mt]));
                }
                uint32_t bhi[8][2], blo[8][2];
#pragma unroll
                for (int p = 0; p < 4; p++) {
                    uint32_t t[4];
                    ldsm4(t, pVhi + rB[p] + (kbb ^ swB[p]));
                    bhi[2*p][0] = t[0]; bhi[2*p+1][0] = t[1];
                    bhi[2*p][1] = t[2]; bhi[2*p+1][1] = t[3];
                    ldsm4(t, pVlo + rB[p] + (kbb ^ swB[p]));
                    blo[2*p][0] = t[0]; blo[2*p+1][0] = t[1];
                    blo[2*p][1] = t[2]; blo[2*p+1][1] = t[3];
                }
#pragma unroll
                for (int mt = 0; mt < 2; mt++)
#pragma unroll
                    for (int nt = 0; nt < 8; nt++) {
                        mma_bf16(acc[mt][nt], ahi[mt], bhi[nt]);
                        mma_bf16(acc[mt][nt], ahi[mt], blo[nt]);
                        mma_bf16(acc[mt][nt], alo[mt], bhi[nt]);
                    }
            }
            __syncthreads();
            if (tid == 0 && gc + NSTAGE < totChunks) fill(gc + NSTAGE);
        }

        // ---- fused epilogue (register accumulators) ----
        const int gB  = cn0 / NV_;
        const int bnd = (gB + 1) * NV_;
        float ssq = 0.f;
#pragma unroll
        for (int mt = 0; mt < 2; mt++) {
            const int row0 = rm0 + warpM * 32 + mt * 16 + (lane >> 2);
            const int row1 = row0 + 8;
            float mx[2][2] = {{-3.0e38f, -3.0e38f}, {-3.0e38f, -3.0e38f}};
#pragma unroll
            for (int nt = 0; nt < 8; nt++) {
                const int c0 = cn0 + warpN * 64 + nt * 8 + (lane & 3) * 2;
#pragma unroll
                for (int e = 0; e < 4; e++) {
                    const int row = (e < 2) ? row0 : row1;
                    const int col = c0 + (e & 1);
                    float sv = acc[mt][nt][e] * invT;
                    float nn = fmaxf(fminf(sv, 0.f), -20.f);
                    ssq += nn * nn;
                    if (row < M_ && col < N_) {
                        int g = (col < bnd) ? 0 : 1;
                        mx[e >> 1][g] = fmaxf(mx[e >> 1][g], sv);
                    }
                }
            }
#pragma unroll
            for (int h = 0; h < 2; h++)
#pragma unroll
                for (int g = 0; g < 2; g++) {
                    float v = mx[h][g];
                    v = fmaxf(v, __shfl_xor_sync(0xffffffffu, v, 1));
                    v = fmaxf(v, __shfl_xor_sync(0xffffffffu, v, 2));
                    mx[h][g] = v;
                }
            if ((lane & 3) == 0) {
                if (row0 < M_) {
                    if (mx[0][0] > -1.0e38f) atomicMax(&g_maxvis[row0 * G_ + gB],     encf(mx[0][0]));
                    if (mx[0][1] > -1.0e38f) atomicMax(&g_maxvis[row0 * G_ + gB + 1], encf(mx[0][1]));
                }
                if (row1 < M_) {
                    if (mx[1][0] > -1.0e38f) atomicMax(&g_maxvis[row1 * G_ + gB],     encf(mx[1][0]));
                    if (mx[1][1] > -1.0e38f) atomicMax(&g_maxvis[row1 * G_ + gB + 1], encf(mx[1][1]));
                }
            }
        }
#pragma unroll
        for (int o = 16; o; o >>= 1) ssq += __shfl_xor_sync(0xffffffffu, ssq, o);
        if (lane == 0) sred[wid] = ssq;
        __syncthreads();
        if (tid == 0) {
            float t = 0.f;
#pragma unroll
            for (int i = 0; i < 8; i++) t += sred[i];
            g_sumsq[s] = t;
        }
        __syncthreads();
    }
}

// ---------------- kernel 3: temporal aggregation ----------------
__global__ void stage2(const float* __restrict__ sfP, const float* __restrict__ thP) {
    const int p = blockIdx.x;
    const int x = p / B_;
    const int y = p % B_;
    const int a = threadIdx.x;

    const float th = 1.0f / (1.0f + expf(-__ldg(thP)));
    const float sf = __ldg(sfP);

    float token = 0.f, sr = 0.f;
    int cnt = 0;
    if (a < NA_) {
        float wsum = 0.f, ws = 0.f;
        const int base = (x * NA_ + a) * G_ + y * T_;
#pragma unroll
        for (int t = 0; t < T_; t++) {
            float m = decf(g_maxvis[base + t]);
            float raw = m - th;
            float sel = fmaxf(raw, 0.f) * sf;
            ws += m * sel;
            wsum += sel;
            cnt += (raw > 0.f) ? 1 : 0;
            if (x == y) sr += 0.5f * (tanhf(20.f * raw) + 1.f);
        }
        token = ws / fmaxf(wsum, 1e-6f);
    }
    __shared__ float st[64], ss[64];
    __shared__ int sc[64];
    st[threadIdx.x] = token; ss[threadIdx.x] = sr; sc[threadIdx.x] = cnt;
    __syncthreads();
    if (threadIdx.x == 0) {
        float ts = 0.f, srs = 0.f; int c = 0;
        for (int i = 0; i < 64; i++) { ts += st[i]; srs += ss[i]; c += sc[i]; }
        g_clip[x * B_ + y] = ts / (float)NA_;
        atomicAdd(&g_fraccnt, c);
        if (x == y) g_selsum[x] = srs;
    }
}

// ---------------- kernel 4: finalize 5 scalars ----------------
__global__ void stage3(float* __restrict__ out,
                       const float* __restrict__ tempP,
                       const float* __restrict__ sfP,
                       const float* __restrict__ thP) {
    const int t = threadIdx.x;
    __shared__ float la[B_], lv[B_];
    __shared__ float sp[32];

    if (t < B_) {
        float m = -3.0e38f;
        for (int j = 0; j < B_; j++) m = fmaxf(m, g_clip[t * B_ + j]);
        float s = 0.f;
        for (int j = 0; j < B_; j++) s += expf(g_clip[t * B_ + j] - m);
        la[t] = -(g_clip[t * B_ + t] - (logf(s) + m));
        float m2 = -3.0e38f;
        for (int j = 0; j < B_; j++) m2 = fmaxf(m2, g_clip[j * B_ + t]);
        float s2 = 0.f;
        for (int j = 0; j < B_; j++) s2 += expf(g_clip[j * B_ + t] - m2);
        lv[t] = -(g_clip[t * B_ + t] - (logf(s2) + m2));
    }
    float acc = 0.f;
    for (int i = t; i < NSUMSQ; i += 32) acc += g_sumsq[i];
    sp[t] = acc;
    __syncthreads();

    if (t == 0) {
        float sumsq = 0.f;
        for (int i = 0; i < 32; i++) sumsq += sp[i];

        float contr = 0.f;
        for (int i = 0; i < B_; i++) contr += la[i] + lv[i];
        contr = contr / (float)B_ * 0.5f;

        float temp = *tempP, sf = *sfP;
        float th = 1.0f / (1.0f + expf(-(*thP)));

        float l_nonneg = sumsq / 56448000.0f;
        float lt = logf(temp);
        float tlow = fmaxf(-lt, 0.f);  tlow *= tlow;
        float thigh = fmaxf(lt - logf(4.0f), 0.f); thigh *= thigh;
        float l_cal = tlow + thigh;
        float a1 = fmaxf(th - 0.9f, 0.f), a2 = fmaxf(0.1f - th, 0.f);
        float l_th = a1 * a1 + a2 * a2;
        float b1 = fmaxf(sf - 20.f, 0.f), b2 = fmaxf(1.f - sf, 0.f);
        float l_sc = b1 * b1 + b2 * b2;
        float reg = 0.15f * l_nonneg + 2.0f * l_cal + 0.1f * l_th + 0.1f * l_sc;

        float frac = (float)g_fraccnt / 288000.0f;

        float selmean = 0.f;
        for (int i = 0; i < B_; i++) selmean += g_selsum[i];
        selmean /= 12000.0f;
        float selrew = -0.1f * log1pf(selmean);

        out[0] = selrew + contr + reg;
        out[1] = contr;
        out[2] = reg;
        out[3] = frac;
        out[4] = selrew;
    }
}

// ---------------- host: tensor maps via driver entry point ----------------
typedef CUresult (*EncTiledFn)(CUtensorMap*, CUtensorMapDataType, cuuint32_t, void*,
                               const cuuint64_t*, const cuuint64_t*, const cuuint32_t*,
                               const cuuint32_t*, CUtensorMapInterleave, CUtensorMapSwizzle,
                               CUtensorMapL2promotion, CUtensorMapFloatOOBfill);

static void make_map(EncTiledFn enc, CUtensorMap* m, void* base, unsigned long long rows) {
    cuuint64_t dims[2]    = {(cuuint64_t)D_, (cuuint64_t)rows};
    cuuint64_t strides[1] = {(cuuint64_t)(D_ * 2)};
    cuuint32_t box[2]     = {64u, 128u};
    cuuint32_t es[2]      = {1u, 1u};
    enc(m, CU_TENSOR_MAP_DATA_TYPE_BFLOAT16, 2, base, dims, strides, box, es,
        CU_TENSOR_MAP_INTERLEAVE_NONE, CU_TENSOR_MAP_SWIZZLE_128B,
        CU_TENSOR_MAP_L2_PROMOTION_L2_128B, CU_TENSOR_MAP_FLOAT_OOB_FILL_NONE);
}

extern "C" void kernel_launch(void* const* d_in, const int* in_sizes, int n_in,
                              void* d_out, int out_size) {
    const float* audio  = (const float*)d_in[0];
    const float* visual = (const float*)d_in[1];
    const float* tempP  = (const float*)d_in[2];
    const float* sfP    = (const float*)d_in[3];
    const float* thP    = (const float*)d_in[4];
    float* out = (float*)d_out;

    void* encPtr = nullptr;
    cudaDriverEntryPointQueryResult qres;
    cudaGetDriverEntryPoint("cuTensorMapEncodeTiled", &encPtr, cudaEnableDefault, &qres);
    EncTiledFn enc = (EncTiledFn)encPtr;

    void *pAhi, *pAlo, *pVhi, *pVlo;
    cudaGetSymbolAddress(&pAhi, g_Ahi);
    cudaGetSymbolAddress(&pAlo, g_Alo);
    cudaGetSymbolAddress(&pVhi, g_Vhi);
    cudaGetSymbolAddress(&pVlo, g_Vlo);

    CUtensorMap tmAhi, tmAlo, tmVhi, tmVlo;
    make_map(enc, &tmAhi, pAhi, M_);
    make_map(enc, &tmAlo, pAlo, M_);
    make_map(enc, &tmVhi, pVhi, N_);
    make_map(enc, &tmVlo, pVlo, N_);

    cudaFuncSetAttribute(gemm_mma, cudaFuncAttributeMaxDynamicSharedMemorySize, SMEM_TOTAL);

    init_kernel<<<(M_ * G_ + 255) / 256, 256>>>();
    norm_split<<<M_, 128>>>(audio, 0);
    norm_split<<<N_, 128>>>(visual, 1);
    gemm_mma<<<GRID_, 256, SMEM_TOTAL>>>(tmAhi, tmAlo, tmVhi, tmVlo, tempP);
    stage2<<<B_ * B_, 64>>>(sfP, thP);
    stage3<<<1, 32>>>(out, tempP, sfP, thP);
}

// round 5
// speedup vs baseline: 2.7806x; 1.0434x over previous
#include <cuda_runtime.h>
#include <cuda.h>
#include <cuda_bf16.h>
#include <cstdint>

#define B_   24
#define NA_  50
#define T_   10
#define NV_  196
#define D_   512
#define M_   (B_*NA_)        // 1200
#define N_   (B_*T_*NV_)     // 47040
#define G_   (B_*T_)         // 240

#define NTM    10            // ceil(1200/128)
#define NTN    368           // ceil(47040/128)
#define NTILES (NTM*NTN)     // 3680
#define NSUMSQ (NTILES*8)    // per-warp partials
#define KCH    8             // 512/64 k-chunks per tile
#define GRID_  148
#define NSTAGE 3

#define TILE_BYTES_  16384   // 128 rows x 64 bf16 x 2B
#define STAGE_BYTES  (4*TILE_BYTES_)          // Ahi, Alo, Vhi, Vlo
#define SMEM_TOTAL   (NSTAGE*STAGE_BYTES)     // 196608

// ---------------- device scratch ----------------
__device__ __align__(128) __nv_bfloat16 g_Ahi[M_*D_];
__device__ __align__(128) __nv_bfloat16 g_Alo[M_*D_];
__device__ __align__(128) __nv_bfloat16 g_Vhi[(size_t)N_*D_];
__device__ __align__(128) __nv_bfloat16 g_Vlo[(size_t)N_*D_];
__device__ unsigned int  g_maxvis[M_*G_];
__device__ float         g_sumsq[NSUMSQ];
__device__ float         g_clip[B_*B_];
__device__ float         g_selsum[B_];
__device__ int           g_fraccnt;

// ---------------- PTX helpers (all non-'a' features) ----------------
__device__ __forceinline__ uint32_t smem_u32(const void* p) {
    uint32_t a;
    asm("{ .reg .u64 t; cvta.to.shared.u64 t, %1; cvt.u32.u64 %0, t; }" : "=r"(a) : "l"(p));
    return a;
}
#define MBARRIER_INIT(a, c) \
    asm volatile("mbarrier.init.shared.b64 [%0], %1;" :: "r"((uint32_t)(a)), "r"((uint32_t)(c)) : "memory")
#define MBARRIER_ARRIVE(a) \
    asm volatile("mbarrier.arrive.shared.b64 _, [%0];" :: "r"((uint32_t)(a)) : "memory")
#define MBARRIER_EXPECT_TX(a, b) \
    asm volatile("mbarrier.arrive.expect_tx.shared.b64 _, [%0], %1;" :: "r"((uint32_t)(a)), "r"((uint32_t)(b)) : "memory")
#define MBARRIER_WAIT_PARITY(a, ph) do { \
    uint32_t _m = (uint32_t)(a); uint32_t _p = (uint32_t)(ph); uint32_t _d; \
    asm volatile("{\n\t.reg .pred p;\n\t" \
        "mbarrier.try_wait.parity.acquire.cta.shared::cta.b64 p, [%1], %2;\n\t" \
        "selp.b32 %0, 1, 0, p;\n\t}" : "=r"(_d) : "r"(_m), "r"(_p) : "memory"); \
    if (!_d) { \
        asm volatile("{\n\t.reg .pred P1;\n\tWL_%=:\n\t" \
            "mbarrier.try_wait.parity.acquire.cta.shared::cta.b64 P1, [%0], %1, 0x989680;\n\t" \
            "@P1 bra.uni WD_%=;\n\tbra.uni WL_%=;\n\tWD_%=:\n\t}" \
            :: "r"(_m), "r"(_p) : "memory"); \
    } } while (0)
#define FENCE_PROXY_ASYNC() asm volatile("fence.proxy.async.shared::cta;" ::: "memory")

__device__ __forceinline__ void tma_ld_2d(uint32_t dst, const CUtensorMap* map,
                                          int cx, int cy, uint32_t mbar) {
    asm volatile(
        "cp.async.bulk.tensor.2d.shared::cta.global.tile.mbarrier::complete_tx::bytes "
        "[%0], [%1, {%2, %3}], [%4];"
        :: "r"(dst), "l"(map), "r"(cx), "r"(cy), "r"(mbar) : "memory");
}
__device__ __forceinline__ void ldsm4(uint32_t r[4], uint32_t addr) {
    asm volatile("ldmatrix.sync.aligned.m8n8.x4.shared.b16 {%0,%1,%2,%3}, [%4];"
        : "=r"(r[0]), "=r"(r[1]), "=r"(r[2]), "=r"(r[3]) : "r"(addr));
}
__device__ __forceinline__ void mma_bf16(float d[4], const uint32_t a[4], const uint32_t b[2]) {
    asm volatile("mma.sync.aligned.m16n8k16.row.col.f32.bf16.bf16.f32 "
        "{%0,%1,%2,%3}, {%4,%5,%6,%7}, {%8,%9}, {%0,%1,%2,%3};"
        : "+f"(d[0]), "+f"(d[1]), "+f"(d[2]), "+f"(d[3])
        : "r"(a[0]), "r"(a[1]), "r"(a[2]), "r"(a[3]), "r"(b[0]), "r"(b[1]));
}

// monotone float<->uint encoding for atomicMax over signed floats
__device__ __forceinline__ unsigned int encf(float f) {
    unsigned int u = __float_as_uint(f);
    return (u & 0x80000000u) ? ~u : (u | 0x80000000u);
}
__device__ __forceinline__ float decf(unsigned int e) {
    unsigned int u = (e & 0x80000000u) ? (e & 0x7fffffffu) : ~e;
    return __uint_as_float(u);
}

// ---------------- kernel 0: init ----------------
__global__ void init_kernel() {
    int i = blockIdx.x * blockDim.x + threadIdx.x;
    if (i < M_ * G_) g_maxvis[i] = 0u;
    if (i == 0) g_fraccnt = 0;
}

// ---------------- kernel 1: L2-normalize + hi/lo bf16 split ----------------
__global__ void norm_split(const float* __restrict__ in, int which) {
    __nv_bfloat16* hi = which ? g_Vhi : g_Ahi;
    __nv_bfloat16* lo = which ? g_Vlo : g_Alo;
    size_t row = blockIdx.x;
    float4 v = reinterpret_cast<const float4*>(in + row * D_)[threadIdx.x];
    float s = v.x * v.x + v.y * v.y + v.z * v.z + v.w * v.w;
#pragma unroll
    for (int o = 16; o; o >>= 1) s += __shfl_xor_sync(0xffffffffu, s, o);
    __shared__ float ws[4];
    __shared__ float sinv;
    if ((threadIdx.x & 31) == 0) ws[threadIdx.x >> 5] = s;
    __syncthreads();
    if (threadIdx.x == 0) sinv = 1.0f / fmaxf(sqrtf(ws[0] + ws[1] + ws[2] + ws[3]), 1e-12f);
    __syncthreads();
    float iv = sinv;
    float x0 = v.x * iv, x1 = v.y * iv, x2 = v.z * iv, x3 = v.w * iv;
    __nv_bfloat16 h0 = __float2bfloat16(x0), h1 = __float2bfloat16(x1);
    __nv_bfloat16 h2 = __float2bfloat16(x2), h3 = __float2bfloat16(x3);
    __nv_bfloat16 l0 = __float2bfloat16(x0 - __bfloat162float(h0));
    __nv_bfloat16 l1 = __float2bfloat16(x1 - __bfloat162float(h1));
    __nv_bfloat16 l2 = __float2bfloat16(x2 - __bfloat162float(h2));
    __nv_bfloat16 l3 = __float2bfloat16(x3 - __bfloat162float(h3));
    __nv_bfloat162 hA; hA.x = h0; hA.y = h1;
    __nv_bfloat162 hB; hB.x = h2; hB.y = h3;
    __nv_bfloat162 lA; lA.x = l0; lA.y = l1;
    __nv_bfloat162 lB; lB.x = l2; lB.y = l3;
    uint2 hu, lu;
    hu.x = *reinterpret_cast<uint32_t*>(&hA); hu.y = *reinterpret_cast<uint32_t*>(&hB);
    lu.x = *reinterpret_cast<uint32_t*>(&lA); lu.y = *reinterpret_cast<uint32_t*>(&lB);
    *reinterpret_cast<uint2*>(hi + row * D_ + threadIdx.x * 4) = hu;
    *reinterpret_cast<uint2*>(lo + row * D_ + threadIdx.x * 4) = lu;
}

// ------- kernel 2: persistent HMMA GEMM, warp-specialized producer -----------
__global__ __launch_bounds__(288, 1)
void gemm_mma(const __grid_constant__ CUtensorMap tmAhi,
              const __grid_constant__ CUtensorMap tmAlo,
              const __grid_constant__ CUtensorMap tmVhi,
              const __grid_constant__ CUtensorMap tmVlo,
              const float* __restrict__ tempP) {
    extern __shared__ __align__(1024) char dsmem[];
    __shared__ uint64_t s_full[NSTAGE], s_empty[NSTAGE];

    const int tid   = threadIdx.x;
    const int lane  = tid & 31;
    const int wid   = tid >> 5;
    const uint32_t sbase = smem_u32(dsmem);
    uint32_t FULL[NSTAGE], EMPTY[NSTAGE];
#pragma unroll
    for (int i = 0; i < NSTAGE; i++) {
        FULL[i]  = smem_u32(&s_full[i]);
        EMPTY[i] = smem_u32(&s_empty[i]);
    }

    if (tid == 0) {
#pragma unroll
        for (int i = 0; i < NSTAGE; i++) {
            MBARRIER_INIT(FULL[i], 1);
            MBARRIER_INIT(EMPTY[i], 8);
        }
        FENCE_PROXY_ASYNC();
    }
    __syncthreads();

    const int bx = blockIdx.x;
    const int ntiles = (NTILES - 1 - bx) / GRID_ + 1;
    const int totChunks = ntiles * KCH;

    // ================= producer warp (single thread) =================
    if (tid == 256) {
        for (int gc = 0; gc < totChunks; gc++) {
            const int st = gc % NSTAGE;
            const int n  = gc / NSTAGE;
            if (n >= 1) MBARRIER_WAIT_PARITY(EMPTY[st], (n - 1) & 1);
            const int s   = bx + (gc / KCH) * GRID_;
            const int c   = gc % KCH;
            const int rm0 = (s % NTM) * 128;
            const int cn0 = (s / NTM) * 128;
            const int k0  = c * 64;
            const uint32_t stg = sbase + st * STAGE_BYTES;
            MBARRIER_EXPECT_TX(FULL[st], STAGE_BYTES);
            tma_ld_2d(stg + 0 * TILE_BYTES_, &tmAhi, k0, rm0, FULL[st]);
            tma_ld_2d(stg + 1 * TILE_BYTES_, &tmAlo, k0, rm0, FULL[st]);
            tma_ld_2d(stg + 2 * TILE_BYTES_, &tmVhi, k0, cn0, FULL[st]);
            tma_ld_2d(stg + 3 * TILE_BYTES_, &tmVlo, k0, cn0, FULL[st]);
        }
        return;
    }
    if (tid > 256) return;

    // ================= consumer warps (0..7) =================
    const int warpM = wid & 3;        // 4 row groups of 32
    const int warpN = wid >> 2;       // 2 col groups of 64
    const float invT = 1.0f / __ldg(tempP);

    // ldmatrix addressing within a 128x64 SW128 tile
    int rA[2], rB[4];
    uint32_t swA[2], swB[4];
#pragma unroll
    for (int mt = 0; mt < 2; mt++) {
        int r = warpM * 32 + mt * 16 + (lane & 15);
        rA[mt] = r * 128; swA[mt] = (r & 7) << 4;
    }
#pragma unroll
    for (int p = 0; p < 4; p++) {
        int r = warpN * 64 + p * 16 + (lane & 15);
        rB[p] = r * 128; swB[p] = (r & 7) << 4;
    }
    const uint32_t laneHi = (lane & 16);

    int gc = 0;
    for (int s = bx; s < NTILES; s += GRID_) {
        const int rm0 = (s % NTM) * 128;
        const int cn0 = (s / NTM) * 128;

        float acc[2][8][4];
#pragma unroll
        for (int mt = 0; mt < 2; mt++)
#pragma unroll
            for (int nt = 0; nt < 8; nt++)
#pragma unroll
                for (int e = 0; e < 4; e++) acc[mt][nt][e] = 0.f;

        for (int c = 0; c < KCH; c++, gc++) {
            const int st = gc % NSTAGE;
            MBARRIER_WAIT_PARITY(FULL[st], (gc / NSTAGE) & 1);
            const uint32_t stg  = sbase + st * STAGE_BYTES;
            const uint32_t pAhi = stg;
            const uint32_t pAlo = stg + 1 * TILE_BYTES_;
            const uint32_t pVhi = stg + 2 * TILE_BYTES_;
            const uint32_t pVlo = stg + 3 * TILE_BYTES_;

#pragma unroll
            for (int ks = 0; ks < 4; ks++) {
                const uint32_t kbb = ks * 32 + laneHi;
                uint32_t ahi[2][4], alo[2][4];
#pragma unroll
                for (int mt = 0; mt < 2; mt++) {
                    ldsm4(ahi[mt], pAhi + rA[mt] + (kbb ^ swA[mt]));
                    ldsm4(alo[mt], pAlo + rA[mt] + (kbb ^ swA[mt]));
                }
                uint32_t bhi[8][2], blo[8][2];
#pragma unroll
                for (int p = 0; p < 4; p++) {
                    uint32_t t[4];
                    ldsm4(t, pVhi + rB[p] + (kbb ^ swB[p]));
                    bhi[2*p][0] = t[0]; bhi[2*p+1][0] = t[1];
                    bhi[2*p][1] = t[2]; bhi[2*p+1][1] = t[3];
                    ldsm4(t, pVlo + rB[p] + (kbb ^ swB[p]));
                    blo[2*p][0] = t[0]; blo[2*p+1][0] = t[1];
                    blo[2*p][1] = t[2]; blo[2*p+1][1] = t[3];
                }
                // term-major: 16 independent MMAs between accumulator reuse
#pragma unroll
                for (int mt = 0; mt < 2; mt++)
#pragma unroll
                    for (int nt = 0; nt < 8; nt++) mma_bf16(acc[mt][nt], ahi[mt], bhi[nt]);
#pragma unroll
                for (int mt = 0; mt < 2; mt++)
#pragma unroll
                    for (int nt = 0; nt < 8; nt++) mma_bf16(acc[mt][nt], ahi[mt], blo[nt]);
#pragma unroll
                for (int mt = 0; mt < 2; mt++)
#pragma unroll
                    for (int nt = 0; nt < 8; nt++) mma_bf16(acc[mt][nt], alo[mt], bhi[nt]);
            }
            if (lane == 0) MBARRIER_ARRIVE(EMPTY[st]);
        }

        // ---- fused epilogue (register accumulators, no CTA sync) ----
        const int gB  = cn0 / NV_;
        const int bnd = (gB + 1) * NV_;
        float ssq = 0.f;
#pragma unroll
        for (int mt = 0; mt < 2; mt++) {
            const int row0 = rm0 + warpM * 32 + mt * 16 + (lane >> 2);
            const int row1 = row0 + 8;
            float mx[2][2] = {{-3.0e38f, -3.0e38f}, {-3.0e38f, -3.0e38f}};
#pragma unroll
            for (int nt = 0; nt < 8; nt++) {
                const int c0 = cn0 + warpN * 64 + nt * 8 + (lane & 3) * 2;
#pragma unroll
                for (int e = 0; e < 4; e++) {
                    const int row = (e < 2) ? row0 : row1;
                    const int col = c0 + (e & 1);
                    float sv = acc[mt][nt][e] * invT;
                    float nn = fmaxf(fminf(sv, 0.f), -20.f);
                    ssq += nn * nn;
                    if (row < M_ && col < N_) {
                        int g = (col < bnd) ? 0 : 1;
                        mx[e >> 1][g] = fmaxf(mx[e >> 1][g], sv);
                    }
                }
            }
#pragma unroll
            for (int h = 0; h < 2; h++)
#pragma unroll
                for (int g = 0; g < 2; g++) {
                    float v = mx[h][g];
                    v = fmaxf(v, __shfl_xor_sync(0xffffffffu, v, 1));
                    v = fmaxf(v, __shfl_xor_sync(0xffffffffu, v, 2));
                    mx[h][g] = v;
                }
            if ((lane & 3) == 0) {
                if (row0 < M_) {
                    if (mx[0][0] > -1.0e38f) atomicMax(&g_maxvis[row0 * G_ + gB],     encf(mx[0][0]));
                    if (mx[0][1] > -1.0e38f) atomicMax(&g_maxvis[row0 * G_ + gB + 1], encf(mx[0][1]));
                }
                if (row1 < M_) {
                    if (mx[1][0] > -1.0e38f) atomicMax(&g_maxvis[row1 * G_ + gB],     encf(mx[1][0]));
                    if (mx[1][1] > -1.0e38f) atomicMax(&g_maxvis[row1 * G_ + gB + 1], encf(mx[1][1]));
                }
            }
        }
#pragma unroll
        for (int o = 16; o; o >>= 1) ssq += __shfl_xor_sync(0xffffffffu, ssq, o);
        if (lane == 0) g_sumsq[s * 8 + wid] = ssq;   // per-warp partial, no sync
    }
}

// ---------------- kernel 3: temporal aggregation ----------------
__global__ void stage2(const float* __restrict__ sfP, const float* __restrict__ thP) {
    const int p = blockIdx.x;
    const int x = p / B_;
    const int y = p % B_;
    const int a = threadIdx.x;

    const float th = 1.0f / (1.0f + expf(-__ldg(thP)));
    const float sf = __ldg(sfP);

    float token = 0.f, sr = 0.f;
    int cnt = 0;
    if (a < NA_) {
        float wsum = 0.f, ws = 0.f;
        const int base = (x * NA_ + a) * G_ + y * T_;
#pragma unroll
        for (int t = 0; t < T_; t++) {
            float m = decf(g_maxvis[base + t]);
            float raw = m - th;
            float sel = fmaxf(raw, 0.f) * sf;
            ws += m * sel;
            wsum += sel;
            cnt += (raw > 0.f) ? 1 : 0;
            if (x == y) sr += 0.5f * (tanhf(20.f * raw) + 1.f);
        }
        token = ws / fmaxf(wsum, 1e-6f);
    }
    __shared__ float st[64], ss[64];
    __shared__ int sc[64];
    st[threadIdx.x] = token; ss[threadIdx.x] = sr; sc[threadIdx.x] = cnt;
    __syncthreads();
    if (threadIdx.x == 0) {
        float ts = 0.f, srs = 0.f; int c = 0;
        for (int i = 0; i < 64; i++) { ts += st[i]; srs += ss[i]; c += sc[i]; }
        g_clip[x * B_ + y] = ts / (float)NA_;
        atomicAdd(&g_fraccnt, c);
        if (x == y) g_selsum[x] = srs;
    }
}

// ---------------- kernel 4: finalize 5 scalars ----------------
__global__ void stage3(float* __restrict__ out,
                       const float* __restrict__ tempP,
                       const float* __restrict__ sfP,
                       const float* __restrict__ thP) {
    const int t = threadIdx.x;
    __shared__ float la[B_], lv[B_];
    __shared__ float sp[32];

    if (t < B_) {
        float m = -3.0e38f;
        for (int j = 0; j < B_; j++) m = fmaxf(m, g_clip[t * B_ + j]);
        float s = 0.f;
        for (int j = 0; j < B_; j++) s += expf(g_clip[t * B_ + j] - m);
        la[t] = -(g_clip[t * B_ + t] - (logf(s) + m));
        float m2 = -3.0e38f;
        for (int j = 0; j < B_; j++) m2 = fmaxf(m2, g_clip[j * B_ + t]);
        float s2 = 0.f;
        for (int j = 0; j < B_; j++) s2 += expf(g_clip[j * B_ + t] - m2);
        lv[t] = -(g_clip[t * B_ + t] - (logf(s2) + m2));
    }
    float acc = 0.f;
    for (int i = t; i < NSUMSQ; i += 32) acc += g_sumsq[i];
    sp[t] = acc;
    __syncthreads();

    if (t == 0) {
        float sumsq = 0.f;
        for (int i = 0; i < 32; i++) sumsq += sp[i];

        float contr = 0.f;
        for (int i = 0; i < B_; i++) contr += la[i] + lv[i];
        contr = contr / (float)B_ * 0.5f;

        float temp = *tempP, sf = *sfP;
        float th = 1.0f / (1.0f + expf(-(*thP)));

        float l_nonneg = sumsq / 56448000.0f;
        float lt = logf(temp);
        float tlow = fmaxf(-lt, 0.f);  tlow *= tlow;
        float thigh = fmaxf(lt - logf(4.0f), 0.f); thigh *= thigh;
        float l_cal = tlow + thigh;
        float a1 = fmaxf(th - 0.9f, 0.f), a2 = fmaxf(0.1f - th, 0.f);
        float l_th = a1 * a1 + a2 * a2;
        float b1 = fmaxf(sf - 20.f, 0.f), b2 = fmaxf(1.f - sf, 0.f);
        float l_sc = b1 * b1 + b2 * b2;
        float reg = 0.15f * l_nonneg + 2.0f * l_cal + 0.1f * l_th + 0.1f * l_sc;

        float frac = (float)g_fraccnt / 288000.0f;

        float selmean = 0.f;
        for (int i = 0; i < B_; i++) selmean += g_selsum[i];
        selmean /= 12000.0f;
        float selrew = -0.1f * log1pf(selmean);

        out[0] = selrew + contr + reg;
        out[1] = contr;
        out[2] = reg;
        out[3] = frac;
        out[4] = selrew;
    }
}

// ---------------- host: tensor maps via driver entry point ----------------
typedef CUresult (*EncTiledFn)(CUtensorMap*, CUtensorMapDataType, cuuint32_t, void*,
                               const cuuint64_t*, const cuuint64_t*, const cuuint32_t*,
                               const cuuint32_t*, CUtensorMapInterleave, CUtensorMapSwizzle,
                               CUtensorMapL2promotion, CUtensorMapFloatOOBfill);

static void make_map(EncTiledFn enc, CUtensorMap* m, void* base, unsigned long long rows) {
    cuuint64_t dims[2]    = {(cuuint64_t)D_, (cuuint64_t)rows};
    cuuint64_t strides[1] = {(cuuint64_t)(D_ * 2)};
    cuuint32_t box[2]     = {64u, 128u};
    cuuint32_t es[2]      = {1u, 1u};
    enc(m, CU_TENSOR_MAP_DATA_TYPE_BFLOAT16, 2, base, dims, strides, box, es,
        CU_TENSOR_MAP_INTERLEAVE_NONE, CU_TENSOR_MAP_SWIZZLE_128B,
        CU_TENSOR_MAP_L2_PROMOTION_L2_128B, CU_TENSOR_MAP_FLOAT_OOB_FILL_NONE);
}

extern "C" void kernel_launch(void* const* d_in, const int* in_sizes, int n_in,
                              void* d_out, int out_size) {
    const float* audio  = (const float*)d_in[0];
    const float* visual = (const float*)d_in[1];
    const float* tempP  = (const float*)d_in[2];
    const float* sfP    = (const float*)d_in[3];
    const float* thP    = (const float*)d_in[4];
    float* out = (float*)d_out;

    void* encPtr = nullptr;
    cudaDriverEntryPointQueryResult qres;
    cudaGetDriverEntryPoint("cuTensorMapEncodeTiled", &encPtr, cudaEnableDefault, &qres);
    EncTiledFn enc = (EncTiledFn)encPtr;

    void *pAhi, *pAlo, *pVhi, *pVlo;
    cudaGetSymbolAddress(&pAhi, g_Ahi);
    cudaGetSymbolAddress(&pAlo, g_Alo);
    cudaGetSymbolAddress(&pVhi, g_Vhi);
    cudaGetSymbolAddress(&pVlo, g_Vlo);

    CUtensorMap tmAhi, tmAlo, tmVhi, tmVlo;
    make_map(enc, &tmAhi, pAhi, M_);
    make_map(enc, &tmAlo, pAlo, M_);
    make_map(enc, &tmVhi, pVhi, N_);
    make_map(enc, &tmVlo, pVlo, N_);

    cudaFuncSetAttribute(gemm_mma, cudaFuncAttributeMaxDynamicSharedMemorySize, SMEM_TOTAL);

    init_kernel<<<(M_ * G_ + 255) / 256, 256>>>();
    norm_split<<<M_, 128>>>(audio, 0);
    norm_split<<<N_, 128>>>(visual, 1);
    gemm_mma<<<GRID_, 288, SMEM_TOTAL>>>(tmAhi, tmAlo, tmVhi, tmVlo, tempP);
    stage2<<<B_ * B_, 64>>>(sfP, thP);
    stage3<<<1, 32>>>(out, tempP, sfP, thP);
}